// round 10
// baseline (speedup 1.0000x reference)
#include <cuda_runtime.h>
#include <cuda_bf16.h>
#include <cstdint>

// Problem constants (PairInitOPM: B=1, L=768, sd=384, pd=128)
#define Lq 768
#define SD 384
#define PD 128
#define SD4 (SD / 4)    // 96 float4 per s row
#define PD4 (PD / 4)    // 32 float4 per wm half-row

// Fused-kernel geometry
#define TI 6            // rows per producer slice
#define NSLICE 128      // 128 slices x 6 rows = 768
#define BI 16
#define BJ 32
#define GX (Lq / BI)    // 48
#define GY (Lq / BJ)    // 24
#define NBLK (GX * GY)  // 1152

// Producer smem: w[2][256*WPAD] + s/sisj[TI*SD4]  (union with consumer q/v)
#define WPAD 5          // 4 data f4 + 1 pad (odd stride -> conflict-free LDS.128)
#define WBUF (256 * WPAD)
#define NTILES_A 24     // 96 f4-k / 4
#define NTILES_B 8      // 32 f4-k / 4
#define SMEM_F4 (2 * WBUF + TI * SD4)      // 2560 + 576 = 3136 f4
#define SMEM_BYTES (SMEM_F4 * 16)          // 50176 B -> 4 blocks/SM

// Scratch (allocation-free rule: __device__ globals; zero-initialized)
__device__ float g_P[Lq * PD];  // si (includes bi)
__device__ float g_Q[Lq * PD];  // sj (includes bj)
__device__ float g_U[Lq * PD];  // zi + bm
__device__ float g_V[Lq * PD];  // zj
__device__ int   g_flag[NSLICE];
__device__ int   g_done;

// ---- async-copy / sync helpers ----
__device__ __forceinline__ void cp_async16(uint32_t dst_smem, const void* src) {
    asm volatile("cp.async.cg.shared.global [%0], [%1], 16;" :: "r"(dst_smem), "l"(src));
}
__device__ __forceinline__ void cp_commit() { asm volatile("cp.async.commit_group;"); }
template <int N>
__device__ __forceinline__ void cp_wait() { asm volatile("cp.async.wait_group %0;" :: "n"(N)); }

__device__ __forceinline__ int ld_acquire(const int* p) {
    int v; asm volatile("ld.acquire.gpu.b32 %0, [%1];" : "=r"(v) : "l"(p)); return v;
}
__device__ __forceinline__ void st_release(int* p, int v) {
    asm volatile("st.release.gpu.b32 [%0], %1;" :: "l"(p), "r"(v));
}

// ---------------------------------------------------------------------------
// Fused kernel: blocks 0..127 first produce P/Q/U/V for their 6-row slice
// (cp.async double-buffered GEMM, R7 structure), publish a flag; then ALL
// 1152 blocks wait only on the slices their 16i x 32j output tile needs and
// run the register-blocked epilogue with streaming stores (R9 structure).
// ---------------------------------------------------------------------------
__global__ __launch_bounds__(256) void k_fused(
    const float* __restrict__ s,
    const float* __restrict__ wi, const float* __restrict__ bi,
    const float* __restrict__ wj, const float* __restrict__ bj,
    const float* __restrict__ wm, const float* __restrict__ bm,
    float* __restrict__ out)
{
    extern __shared__ float4 sm4[];
    const int t   = threadIdx.x;
    const int bid = blockIdx.x;

    // ===================== PRODUCER (bids 0..127) =====================
    if (bid < NSLICE) {
        float4* w_sh4 = sm4;                 // [2][WBUF]
        float4* s_sh4 = sm4 + 2 * WBUF;      // [TI][SD4]; overlaid by sisj in B
        const int i0 = bid * TI;
        const uint32_t w_sm = (uint32_t)__cvta_generic_to_shared(w_sh4);
        const int sc  = t >> 2;              // staged column base (0..63), step 64
        const int sm_ = t & 3;               // f4 index within 4-f4 k-tile

        const float4* __restrict__ S4 = (const float4*)s;
        for (int idx = t; idx < TI * SD4; idx += 256)
            s_sh4[idx] = S4[i0 * SD4 + idx];

        float acc[TI];
#pragma unroll
        for (int r = 0; r < TI; r++) acc[r] = 0.f;

        // ---- Phase A: si|sj = s @ [wi;wj]^T ----
        auto stageA = [&](int tile, int b) {
            const int kq0 = tile * 4;
#pragma unroll
            for (int it = 0; it < 4; it++) {
                int c = sc + 64 * it;
                const float* wr = (c < PD) ? (wi + c * SD) : (wj + (c - PD) * SD);
                cp_async16(w_sm + (uint32_t)((b * WBUF + c * WPAD + sm_) * 16),
                           (const float4*)wr + kq0 + sm_);
            }
            cp_commit();
        };

        stageA(0, 0);
        for (int tile = 0; tile < NTILES_A; tile++) {
            if (tile + 1 < NTILES_A) { stageA(tile + 1, (tile + 1) & 1); cp_wait<1>(); }
            else                     { cp_wait<0>(); }
            __syncthreads();
            const float4* wb = w_sh4 + (tile & 1) * WBUF;
            const int kq0 = tile * 4;
#pragma unroll
            for (int m = 0; m < 4; m++) {
                float4 w4 = wb[t * WPAD + m];              // conflict-free
#pragma unroll
                for (int r = 0; r < TI; r++) {
                    float4 s4 = s_sh4[r * SD4 + kq0 + m];  // broadcast
                    acc[r] = fmaf(s4.x, w4.x, acc[r]);
                    acc[r] = fmaf(s4.y, w4.y, acc[r]);
                    acc[r] = fmaf(s4.z, w4.z, acc[r]);
                    acc[r] = fmaf(s4.w, w4.w, acc[r]);
                }
            }
            __syncthreads();
        }

        {
            float b = (t < PD) ? bi[t] : bj[t - PD];
#pragma unroll
            for (int r = 0; r < TI; r++) acc[r] += b;
        }

        // sisj overlays the dead s_sh region (all phase-A reads done)
        float4* sisj4 = s_sh4;               // [TI][64 f4]
        float*  sisj  = (float*)sisj4;
#pragma unroll
        for (int r = 0; r < TI; r++) sisj[r * 256 + t] = acc[r];

        // ---- Phase B: zi/zj via wm halves ----
        const int which = t >> 7;
        const int e     = t & 127;
        float az[TI];
#pragma unroll
        for (int r = 0; r < TI; r++) az[r] = 0.f;

        auto stageB = [&](int tile, int b) {
            const int kq0 = tile * 4;
#pragma unroll
            for (int it = 0; it < 4; it++) {
                int c = sc + 64 * it;
                const float4* wr4 = (const float4*)wm + (c & 127) * 64 + (c >> 7) * 32;
                cp_async16(w_sm + (uint32_t)((b * WBUF + c * WPAD + sm_) * 16),
                           wr4 + kq0 + sm_);
            }
            cp_commit();
        };

        stageB(0, 0);
        for (int tile = 0; tile < NTILES_B; tile++) {
            if (tile + 1 < NTILES_B) { stageB(tile + 1, (tile + 1) & 1); cp_wait<1>(); }
            else                     { cp_wait<0>(); }
            __syncthreads();                 // also publishes sisj (tile 0)
            const float4* wb = w_sh4 + (tile & 1) * WBUF;
            const int kq0 = tile * 4;
#pragma unroll
            for (int m = 0; m < 4; m++) {
                float4 w4 = wb[t * WPAD + m];
#pragma unroll
                for (int r = 0; r < TI; r++) {
                    float4 z4 = sisj4[r * 64 + which * 32 + kq0 + m];  // broadcast
                    az[r] = fmaf(z4.x, w4.x, az[r]);
                    az[r] = fmaf(z4.y, w4.y, az[r]);
                    az[r] = fmaf(z4.z, w4.z, az[r]);
                    az[r] = fmaf(z4.w, w4.w, az[r]);
                }
            }
            __syncthreads();
        }

        const float bmv = bm[e];
#pragma unroll
        for (int r = 0; r < TI; r++) {
            int i = i0 + r;
            if (which == 0) {
                g_P[i * PD + e] = acc[r];
                g_U[i * PD + e] = az[r] + bmv;
            } else {
                g_Q[i * PD + e] = acc[r];
                g_V[i * PD + e] = az[r];
            }
        }

        __syncthreads();                     // whole block's stores issued
        if (t == 0) {
            __threadfence();                 // make them GPU-visible
            st_release(&g_flag[bid], 1);     // publish slice
        }
        __syncthreads();                     // smem reuse below is safe
    }

    // ===================== CONSUMER (all 1152 blocks) =====================
    const int bx = bid % GX;                 // i-tile
    const int by = bid / GX;                 // j-tile
    const int tx = t & 31;                   // d quad
    const int ty = t >> 5;                   // 0..7
    const int i1 = bx * BI + ty;
    const int i2 = i1 + 8;
    const int j0 = by * BJ;

    // Wait for the slices this tile needs (thread 0 polls, barrier hands off)
    if (t == 0) {
        const int si0 = (bx * BI) / TI, si1 = (bx * BI + BI - 1) / TI;
        for (int sx = si0; sx <= si1; sx++)
            while (ld_acquire(&g_flag[sx]) == 0) __nanosleep(128);
        const int sj0 = (by * BJ) / TI, sj1 = (by * BJ + BJ - 1) / TI;
        for (int sx = sj0; sx <= sj1; sx++)
            while (ld_acquire(&g_flag[sx]) == 0) __nanosleep(128);
    }
    __syncthreads();

    float4* q_sh = sm4;                      // reuse smem union
    float4* v_sh = sm4 + BJ * 32;

    const float4* __restrict__ P4 = (const float4*)g_P;
    const float4* __restrict__ Q4 = (const float4*)g_Q;
    const float4* __restrict__ U4 = (const float4*)g_U;
    const float4* __restrict__ V4 = (const float4*)g_V;

#pragma unroll
    for (int m = 0; m < (BJ * 32) / 256; m++) {
        int idx = t + m * 256;
        q_sh[idx] = Q4[j0 * 32 + idx];
        v_sh[idx] = V4[j0 * 32 + idx];
    }

    const float4 p1 = P4[i1 * 32 + tx];
    const float4 u1 = U4[i1 * 32 + tx];
    const float4 p2 = P4[i2 * 32 + tx];
    const float4 u2 = U4[i2 * 32 + tx];
    __syncthreads();

    float4* out4 = (float4*)out;
    size_t base1 = ((size_t)i1 * Lq + j0) * 32 + tx;
    size_t base2 = ((size_t)i2 * Lq + j0) * 32 + tx;

#pragma unroll 8
    for (int jj = 0; jj < BJ; jj++) {
        float4 q = q_sh[jj * 32 + tx];       // LDS.128, conflict-free
        float4 v = v_sh[jj * 32 + tx];
        float4 o1, o2;
        o1.x = fmaf(p1.x, q.x, u1.x + v.x);
        o1.y = fmaf(p1.y, q.y, u1.y + v.y);
        o1.z = fmaf(p1.z, q.z, u1.z + v.z);
        o1.w = fmaf(p1.w, q.w, u1.w + v.w);
        o2.x = fmaf(p2.x, q.x, u2.x + v.x);
        o2.y = fmaf(p2.y, q.y, u2.y + v.y);
        o2.z = fmaf(p2.z, q.z, u2.z + v.z);
        o2.w = fmaf(p2.w, q.w, u2.w + v.w);
        __stcs(&out4[base1 + (size_t)jj * 32], o1);   // streaming stores
        __stcs(&out4[base2 + (size_t)jj * 32], o2);
    }

    // ---- cleanup: last block resets flags so graph replays start clean ----
    if (t == 0) {
        if (atomicAdd(&g_done, 1) == NBLK - 1) {
            for (int sx = 0; sx < NSLICE; sx++) g_flag[sx] = 0;
            g_done = 0;
        }
    }
}

// ---------------------------------------------------------------------------
extern "C" void kernel_launch(void* const* d_in, const int* in_sizes, int n_in,
                              void* d_out, int out_size)
{
    const float* s  = (const float*)d_in[0];
    const float* wi = (const float*)d_in[1];
    const float* bi = (const float*)d_in[2];
    const float* wj = (const float*)d_in[3];
    const float* bj = (const float*)d_in[4];
    const float* wm = (const float*)d_in[5];
    const float* bm = (const float*)d_in[6];
    float* out = (float*)d_out;

    // Idempotent, deterministic, not an allocation: raise dynamic-smem cap.
    cudaFuncSetAttribute(k_fused, cudaFuncAttributeMaxDynamicSharedMemorySize,
                         SMEM_BYTES);

    k_fused<<<NBLK, 256, SMEM_BYTES>>>(s, wi, bi, wj, bj, wm, bm, out);
}

// round 11
// speedup vs baseline: 1.0579x; 1.0579x over previous
#include <cuda_runtime.h>
#include <cuda_bf16.h>
#include <cstdint>

// Problem constants (PairInitOPM: B=1, L=768, sd=384, pd=128)
#define Lq 768
#define SD 384
#define PD 128
#define SD4 (SD / 4)   // 96 float4 per s row
#define PD4 (PD / 4)   // 32 float4 per wm half-row

// Scratch (allocation-free rule: __device__ globals)
__device__ float g_P[Lq * PD];  // si  (includes bi)
__device__ float g_Q[Lq * PD];  // sj  (includes bj)
__device__ float g_U[Lq * PD];  // zi + bm
__device__ float g_V[Lq * PD];  // zj

// ---- cp.async helpers ----
__device__ __forceinline__ void cp_async16(uint32_t dst_smem, const void* src) {
    asm volatile("cp.async.cg.shared.global [%0], [%1], 16;" :: "r"(dst_smem), "l"(src));
}
__device__ __forceinline__ void cp_commit() { asm volatile("cp.async.commit_group;"); }
template <int N>
__device__ __forceinline__ void cp_wait() { asm volatile("cp.async.wait_group %0;" :: "n"(N)); }

// ---------------------------------------------------------------------------
// Kernel 1: EXACT R7 config (best measured of 6 designs).
// TI=6 rows/block -> 128 blocks = one wave. cp.async double-buffered weight
// tiles from original layout; float4 smem compute reads.
// ---------------------------------------------------------------------------
#define TI 6
#define WPAD 9                     // float4 per col slot (8 data + 1 pad)
#define WBUF (256 * WPAD)          // float4 per buffer
#define NTA 12                     // phase-A tiles (96 float4-k / 8)
#define NTB 4                      // phase-B tiles (32 float4-k / 8)
#define K1_SMEM_BYTES ((2 * WBUF + TI * SD4 + TI * 64) * 16)

__global__ __launch_bounds__(256) void k1_proj(
    const float* __restrict__ s,
    const float* __restrict__ wi, const float* __restrict__ bi,
    const float* __restrict__ wj, const float* __restrict__ bj,
    const float* __restrict__ wm, const float* __restrict__ bm)
{
    extern __shared__ float4 sm4[];
    float4* w_sh4  = sm4;                        // [2][256*WPAD]
    float4* s_sh4  = sm4 + 2 * WBUF;             // [TI][SD4]
    float4* sisj4  = s_sh4 + TI * SD4;           // [TI][64]

    const int t  = threadIdx.x;                  // output column c = t
    const int i0 = blockIdx.x * TI;
    const uint32_t w_sm = (uint32_t)__cvta_generic_to_shared(w_sh4);

    const int sc = t >> 3;                       // base col (0..31), step 32
    const int sm_ = t & 7;                       // float4 index within tile

    const float4* __restrict__ S4 = (const float4*)s;
    for (int idx = t; idx < TI * SD4; idx += 256)
        s_sh4[idx] = S4[i0 * SD4 + idx];

    float acc[TI];
#pragma unroll
    for (int r = 0; r < TI; r++) acc[r] = 0.f;

    // ---------------- Phase A ----------------
    auto stageA = [&](int tile, int b) {
        const int kq0 = tile * 8;
#pragma unroll
        for (int it = 0; it < 8; it++) {
            int c = sc + 32 * it;
            const float* wr = (c < PD) ? (wi + c * SD) : (wj + (c - PD) * SD);
            cp_async16(w_sm + (uint32_t)((b * WBUF + c * WPAD + sm_) * 16),
                       (const float4*)wr + kq0 + sm_);
        }
        cp_commit();
    };

    stageA(0, 0);
    for (int tile = 0; tile < NTA; tile++) {
        if (tile + 1 < NTA) { stageA(tile + 1, (tile + 1) & 1); cp_wait<1>(); }
        else                { cp_wait<0>(); }
        __syncthreads();
        const float4* wb = w_sh4 + (tile & 1) * WBUF;
        const int kq0 = tile * 8;
#pragma unroll
        for (int m = 0; m < 8; m++) {
            float4 w4 = wb[t * WPAD + m];
#pragma unroll
            for (int r = 0; r < TI; r++) {
                float4 s4 = s_sh4[r * SD4 + kq0 + m];
                acc[r] = fmaf(s4.x, w4.x, acc[r]);
                acc[r] = fmaf(s4.y, w4.y, acc[r]);
                acc[r] = fmaf(s4.z, w4.z, acc[r]);
                acc[r] = fmaf(s4.w, w4.w, acc[r]);
            }
        }
        __syncthreads();
    }

    {
        float b = (t < PD) ? bi[t] : bj[t - PD];
#pragma unroll
        for (int r = 0; r < TI; r++) acc[r] += b;
    }

    float* sisj = (float*)sisj4;
#pragma unroll
    for (int r = 0; r < TI; r++) sisj[r * 256 + t] = acc[r];

    // ---------------- Phase B ----------------
    const int which = t >> 7;
    const int e     = t & 127;
    float az[TI];
#pragma unroll
    for (int r = 0; r < TI; r++) az[r] = 0.f;

    auto stageB = [&](int tile, int b) {
        const int kq0 = tile * 8;
#pragma unroll
        for (int it = 0; it < 8; it++) {
            int c = sc + 32 * it;
            const float* wr = wm + (c & 127) * (2 * PD) + (c >> 7) * PD;
            cp_async16(w_sm + (uint32_t)((b * WBUF + c * WPAD + sm_) * 16),
                       (const float4*)wr + kq0 + sm_);
        }
        cp_commit();
    };

    stageB(0, 0);
    for (int tile = 0; tile < NTB; tile++) {
        if (tile + 1 < NTB) { stageB(tile + 1, (tile + 1) & 1); cp_wait<1>(); }
        else                { cp_wait<0>(); }
        __syncthreads();
        const float4* wb = w_sh4 + (tile & 1) * WBUF;
        const int kq0 = tile * 8;
#pragma unroll
        for (int m = 0; m < 8; m++) {
            float4 w4 = wb[t * WPAD + m];
#pragma unroll
            for (int r = 0; r < TI; r++) {
                float4 z4 = sisj4[r * 64 + which * 32 + kq0 + m];
                az[r] = fmaf(z4.x, w4.x, az[r]);
                az[r] = fmaf(z4.y, w4.y, az[r]);
                az[r] = fmaf(z4.z, w4.z, az[r]);
                az[r] = fmaf(z4.w, w4.w, az[r]);
            }
        }
        __syncthreads();
    }

    const float bmv = bm[e];
#pragma unroll
    for (int r = 0; r < TI; r++) {
        int i = i0 + r;
        if (which == 0) {
            g_P[i * PD + e] = acc[r];
            g_U[i * PD + e] = az[r] + bmv;
        } else {
            g_Q[i * PD + e] = acc[r];
            g_V[i * PD + e] = az[r];
        }
    }
}

// ---------------------------------------------------------------------------
// Kernel 2: z0[i,j,d] = U[i,d] + V[j,d] + P[i,d]*Q[j,d]
// FOUR i rows per thread (i, i+8, i+16, i+24): each q/v LDS pair feeds 4
// stores -> L1 wavefronts per store drop 8 -> 6. Tile = 32 i x 32 j,
// 256 threads, 32 KB smem, 576 blocks. Streaming float4 stores.
// ---------------------------------------------------------------------------
#define BI 32
#define BJ 32
#define NR 4

__global__ __launch_bounds__(256) void k2_outer(float* __restrict__ out)
{
    __shared__ float4 q_sh[BJ * 32];   // 16 KB
    __shared__ float4 v_sh[BJ * 32];   // 16 KB

    const int t  = threadIdx.x;
    const int tx = t & 31;             // d quad: d = 4*tx
    const int ty = t >> 5;             // 0..7
    const int j0 = blockIdx.y * BJ;

    int irow[NR];
#pragma unroll
    for (int r = 0; r < NR; r++) irow[r] = blockIdx.x * BI + ty + r * 8;

    const float4* __restrict__ P4 = (const float4*)g_P;
    const float4* __restrict__ Q4 = (const float4*)g_Q;
    const float4* __restrict__ U4 = (const float4*)g_U;
    const float4* __restrict__ V4 = (const float4*)g_V;

#pragma unroll
    for (int m = 0; m < (BJ * 32) / 256; m++) {
        int idx = t + m * 256;
        q_sh[idx] = Q4[j0 * 32 + idx];
        v_sh[idx] = V4[j0 * 32 + idx];
    }

    float4 p[NR], u[NR];
#pragma unroll
    for (int r = 0; r < NR; r++) {
        p[r] = P4[irow[r] * 32 + tx];
        u[r] = U4[irow[r] * 32 + tx];
    }
    __syncthreads();

    float4* out4 = (float4*)out;
    size_t base[NR];
#pragma unroll
    for (int r = 0; r < NR; r++)
        base[r] = ((size_t)irow[r] * Lq + j0) * 32 + tx;

#pragma unroll 4
    for (int jj = 0; jj < BJ; jj++) {
        float4 q = q_sh[jj * 32 + tx];     // LDS.128, conflict-free
        float4 v = v_sh[jj * 32 + tx];
#pragma unroll
        for (int r = 0; r < NR; r++) {
            float4 o;
            o.x = fmaf(p[r].x, q.x, u[r].x + v.x);
            o.y = fmaf(p[r].y, q.y, u[r].y + v.y);
            o.z = fmaf(p[r].z, q.z, u[r].z + v.z);
            o.w = fmaf(p[r].w, q.w, u[r].w + v.w);
            __stcs(&out4[base[r] + (size_t)jj * 32], o);  // streaming store
        }
    }
}

// ---------------------------------------------------------------------------
extern "C" void kernel_launch(void* const* d_in, const int* in_sizes, int n_in,
                              void* d_out, int out_size)
{
    const float* s  = (const float*)d_in[0];
    const float* wi = (const float*)d_in[1];
    const float* bi = (const float*)d_in[2];
    const float* wj = (const float*)d_in[3];
    const float* bj = (const float*)d_in[4];
    const float* wm = (const float*)d_in[5];
    const float* bm = (const float*)d_in[6];
    float* out = (float*)d_out;

    // Idempotent, deterministic, not an allocation: raise dynamic-smem cap.
    cudaFuncSetAttribute(k1_proj, cudaFuncAttributeMaxDynamicSharedMemorySize,
                         K1_SMEM_BYTES);

    k1_proj<<<Lq / TI, 256, K1_SMEM_BYTES>>>(s, wi, bi, wj, bj, wm, bm);

    dim3 grid2(Lq / BI, Lq / BJ);
    k2_outer<<<grid2, 256>>>(out);
}

// round 12
// speedup vs baseline: 1.1001x; 1.0398x over previous
#include <cuda_runtime.h>
#include <cuda_bf16.h>
#include <cstdint>

// Problem constants (PairInitOPM: B=1, L=768, sd=384, pd=128)
#define Lq 768
#define SD 384
#define PD 128
#define SD4 (SD / 4)   // 96 float4 per s row
#define PD4 (PD / 4)   // 32 float4 per wm half-row

// Scratch (allocation-free rule: __device__ globals)
__device__ float g_P[Lq * PD];  // si  (includes bi)
__device__ float g_Q[Lq * PD];  // sj  (includes bj)
__device__ float g_U[Lq * PD];  // zi + bm
__device__ float g_V[Lq * PD];  // zj

// ---- cp.async helpers ----
__device__ __forceinline__ void cp_async16(uint32_t dst_smem, const void* src) {
    asm volatile("cp.async.cg.shared.global [%0], [%1], 16;" :: "r"(dst_smem), "l"(src));
}
__device__ __forceinline__ void cp_commit() { asm volatile("cp.async.commit_group;"); }
template <int N>
__device__ __forceinline__ void cp_wait() { asm volatile("cp.async.wait_group %0;" :: "n"(N)); }

// ---- packed f32x2 FMA; operands come from float4-aliased register pairs ----
__device__ __forceinline__ uint64_t fma2(uint64_t a, uint64_t b, uint64_t c) {
    uint64_t d; asm("fma.rn.f32x2 %0, %1, %2, %3;" : "=l"(d) : "l"(a), "l"(b), "l"(c));
    return d;
}
union F4U { float4 f; ulonglong2 u; };

// ---------------------------------------------------------------------------
// Kernel 1: R7 structure (cp.async double-buffered weight tiles) with the
// inner product done in fma.rn.f32x2 — float4 smem loads already produce
// aligned register pairs, so no packing MOVs are needed.
// TI=6 rows/block -> 128 blocks = one wave.
// ---------------------------------------------------------------------------
#define TI 6
#define WPAD 9                     // float4 per col slot (8 data + 1 pad)
#define WBUF (256 * WPAD)          // float4 per buffer
#define NTA 12                     // phase-A tiles (96 float4-k / 8)
#define NTB 4                      // phase-B tiles (32 float4-k / 8)
#define K1_SMEM_BYTES ((2 * WBUF + TI * SD4 + TI * 64) * 16)

__global__ __launch_bounds__(256) void k1_proj(
    const float* __restrict__ s,
    const float* __restrict__ wi, const float* __restrict__ bi,
    const float* __restrict__ wj, const float* __restrict__ bj,
    const float* __restrict__ wm, const float* __restrict__ bm)
{
    extern __shared__ float4 sm4[];
    float4* w_sh4  = sm4;                        // [2][256*WPAD]
    float4* s_sh4  = sm4 + 2 * WBUF;             // [TI][SD4]
    float4* sisj4  = s_sh4 + TI * SD4;           // [TI][64]

    const int t  = threadIdx.x;                  // output column c = t
    const int i0 = blockIdx.x * TI;
    const uint32_t w_sm = (uint32_t)__cvta_generic_to_shared(w_sh4);

    const int sc = t >> 3;                       // base col (0..31), step 32
    const int sm_ = t & 7;                       // float4 index within tile

    const float4* __restrict__ S4 = (const float4*)s;
    for (int idx = t; idx < TI * SD4; idx += 256)
        s_sh4[idx] = S4[i0 * SD4 + idx];

    uint64_t acc2[TI];
#pragma unroll
    for (int r = 0; r < TI; r++) acc2[r] = 0ull;

    // ---------------- Phase A ----------------
    auto stageA = [&](int tile, int b) {
        const int kq0 = tile * 8;
#pragma unroll
        for (int it = 0; it < 8; it++) {
            int c = sc + 32 * it;
            const float* wr = (c < PD) ? (wi + c * SD) : (wj + (c - PD) * SD);
            cp_async16(w_sm + (uint32_t)((b * WBUF + c * WPAD + sm_) * 16),
                       (const float4*)wr + kq0 + sm_);
        }
        cp_commit();
    };

    stageA(0, 0);
    for (int tile = 0; tile < NTA; tile++) {
        if (tile + 1 < NTA) { stageA(tile + 1, (tile + 1) & 1); cp_wait<1>(); }
        else                { cp_wait<0>(); }
        __syncthreads();
        const float4* wb = w_sh4 + (tile & 1) * WBUF;
        const int kq0 = tile * 8;
#pragma unroll
        for (int m = 0; m < 8; m++) {
            F4U w4; w4.f = wb[t * WPAD + m];     // conflict-free LDS.128
#pragma unroll
            for (int r = 0; r < TI; r++) {
                F4U s4; s4.f = s_sh4[r * SD4 + kq0 + m];   // broadcast LDS.128
                acc2[r] = fma2(s4.u.x, w4.u.x, acc2[r]);
                acc2[r] = fma2(s4.u.y, w4.u.y, acc2[r]);
            }
        }
        __syncthreads();
    }

    float acc[TI];
    {
        float b = (t < PD) ? bi[t] : bj[t - PD];
#pragma unroll
        for (int r = 0; r < TI; r++) {
            float2 v = *(float2*)&acc2[r];       // aliased register pair
            acc[r] = v.x + v.y + b;
        }
    }

    float* sisj = (float*)sisj4;
#pragma unroll
    for (int r = 0; r < TI; r++) sisj[r * 256 + t] = acc[r];

    // ---------------- Phase B ----------------
    const int which = t >> 7;
    const int e     = t & 127;
    uint64_t az2[TI];
#pragma unroll
    for (int r = 0; r < TI; r++) az2[r] = 0ull;

    auto stageB = [&](int tile, int b) {
        const int kq0 = tile * 8;
#pragma unroll
        for (int it = 0; it < 8; it++) {
            int c = sc + 32 * it;
            const float* wr = wm + (c & 127) * (2 * PD) + (c >> 7) * PD;
            cp_async16(w_sm + (uint32_t)((b * WBUF + c * WPAD + sm_) * 16),
                       (const float4*)wr + kq0 + sm_);
        }
        cp_commit();
    };

    stageB(0, 0);
    for (int tile = 0; tile < NTB; tile++) {
        if (tile + 1 < NTB) { stageB(tile + 1, (tile + 1) & 1); cp_wait<1>(); }
        else                { cp_wait<0>(); }
        __syncthreads();                          // also publishes sisj (tile 0)
        const float4* wb = w_sh4 + (tile & 1) * WBUF;
        const int kq0 = tile * 8;
#pragma unroll
        for (int m = 0; m < 8; m++) {
            F4U w4; w4.f = wb[t * WPAD + m];
#pragma unroll
            for (int r = 0; r < TI; r++) {
                F4U z4; z4.f = sisj4[r * 64 + which * 32 + kq0 + m];  // broadcast
                az2[r] = fma2(z4.u.x, w4.u.x, az2[r]);
                az2[r] = fma2(z4.u.y, w4.u.y, az2[r]);
            }
        }
        __syncthreads();
    }

    const float bmv = bm[e];
#pragma unroll
    for (int r = 0; r < TI; r++) {
        float2 v = *(float2*)&az2[r];
        float z = v.x + v.y;
        int i = i0 + r;
        if (which == 0) {
            g_P[i * PD + e] = acc[r];
            g_U[i * PD + e] = z + bmv;
        } else {
            g_Q[i * PD + e] = acc[r];
            g_V[i * PD + e] = z;
        }
    }
}

// ---------------------------------------------------------------------------
// Kernel 2: EXACT R9 config (best measured: 46.3us @ 66.3% DRAM).
// TWO i rows per thread (i, i+8); 16 i x 32 j tile; streaming float4 stores.
// ---------------------------------------------------------------------------
#define BI 16
#define BJ 32

__global__ __launch_bounds__(256) void k2_outer(float* __restrict__ out)
{
    __shared__ float4 q_sh[BJ * 32];   // 16 KB
    __shared__ float4 v_sh[BJ * 32];   // 16 KB

    const int t  = threadIdx.x;
    const int tx = t & 31;             // d quad: d = 4*tx
    const int ty = t >> 5;             // 0..7
    const int i1 = blockIdx.x * BI + ty;
    const int i2 = i1 + 8;
    const int j0 = blockIdx.y * BJ;

    const float4* __restrict__ P4 = (const float4*)g_P;
    const float4* __restrict__ Q4 = (const float4*)g_Q;
    const float4* __restrict__ U4 = (const float4*)g_U;
    const float4* __restrict__ V4 = (const float4*)g_V;

#pragma unroll
    for (int m = 0; m < (BJ * 32) / 256; m++) {
        int idx = t + m * 256;
        q_sh[idx] = Q4[j0 * 32 + idx];
        v_sh[idx] = V4[j0 * 32 + idx];
    }

    const float4 p1 = P4[i1 * 32 + tx];
    const float4 u1 = U4[i1 * 32 + tx];
    const float4 p2 = P4[i2 * 32 + tx];
    const float4 u2 = U4[i2 * 32 + tx];
    __syncthreads();

    float4* out4 = (float4*)out;
    size_t base1 = ((size_t)i1 * Lq + j0) * 32 + tx;
    size_t base2 = ((size_t)i2 * Lq + j0) * 32 + tx;

#pragma unroll 8
    for (int jj = 0; jj < BJ; jj++) {
        float4 q = q_sh[jj * 32 + tx];     // LDS.128, conflict-free
        float4 v = v_sh[jj * 32 + tx];
        float4 o1, o2;
        o1.x = fmaf(p1.x, q.x, u1.x + v.x);
        o1.y = fmaf(p1.y, q.y, u1.y + v.y);
        o1.z = fmaf(p1.z, q.z, u1.z + v.z);
        o1.w = fmaf(p1.w, q.w, u1.w + v.w);
        o2.x = fmaf(p2.x, q.x, u2.x + v.x);
        o2.y = fmaf(p2.y, q.y, u2.y + v.y);
        o2.z = fmaf(p2.z, q.z, u2.z + v.z);
        o2.w = fmaf(p2.w, q.w, u2.w + v.w);
        __stcs(&out4[base1 + (size_t)jj * 32], o1);  // streaming stores
        __stcs(&out4[base2 + (size_t)jj * 32], o2);
    }
}

// ---------------------------------------------------------------------------
extern "C" void kernel_launch(void* const* d_in, const int* in_sizes, int n_in,
                              void* d_out, int out_size)
{
    const float* s  = (const float*)d_in[0];
    const float* wi = (const float*)d_in[1];
    const float* bi = (const float*)d_in[2];
    const float* wj = (const float*)d_in[3];
    const float* bj = (const float*)d_in[4];
    const float* wm = (const float*)d_in[5];
    const float* bm = (const float*)d_in[6];
    float* out = (float*)d_out;

    // Idempotent, deterministic, not an allocation: raise dynamic-smem cap.
    cudaFuncSetAttribute(k1_proj, cudaFuncAttributeMaxDynamicSharedMemorySize,
                         K1_SMEM_BYTES);

    k1_proj<<<Lq / TI, 256, K1_SMEM_BYTES>>>(s, wi, bi, wj, bj, wm, bm);

    dim3 grid2(Lq / BI, Lq / BJ);
    k2_outer<<<grid2, 256>>>(out);
}